// round 1
// baseline (speedup 1.0000x reference)
#include <cuda_runtime.h>
#include <math.h>

#define BB 32
#define LL 2048
#define DD 512
#define DFF 256
#define NBLK 6
#define EPSN 1e-6f
#define LSPLIT 16
#define LCHUNK (LL / LSPLIT)   // 128
#define SCALE 0.04419417382415922f  // 1/sqrt(512)

// -------- device scratch (no allocations allowed) --------
__device__ float g_scores[BB * LL];              // 256 KB
__device__ float g_Apart[LSPLIT][BB][DD];        // 1 MB, deterministic partials
__device__ float g_q[BB * DD];                   // running q state

// -------- init: copy q input into state --------
__global__ void k_init_q(const float* __restrict__ q) {
    int i = blockIdx.x * 256 + threadIdx.x;
    if (i < BB * DD) g_q[i] = q[i];
}

// -------- K1: scores[b,l] = <q_b, k[b,l]> * scale --------
// grid (LL/8, BB), block 256 (8 warps, 1 warp per l-row, 2KB coalesced reads)
__global__ void k_scores(const float* __restrict__ k) {
    __shared__ float sq[DD];
    const int b = blockIdx.y;
    const int tid = threadIdx.x;
    sq[tid]       = g_q[b * DD + tid];
    sq[tid + 256] = g_q[b * DD + tid + 256];
    __syncthreads();

    const int w = tid >> 5, lane = tid & 31;
    const int l = blockIdx.x * 8 + w;
    const float4* __restrict__ k4 = (const float4*)(k + (size_t)b * LL * DD + (size_t)l * DD);
    const float4* q4 = (const float4*)sq;

    float s = 0.f;
#pragma unroll
    for (int j = 0; j < 4; j++) {
        float4 kv = k4[lane + 32 * j];
        float4 qv = q4[lane + 32 * j];
        s += kv.x * qv.x + kv.y * qv.y + kv.z * qv.z + kv.w * qv.w;
    }
#pragma unroll
    for (int o = 16; o > 0; o >>= 1) s += __shfl_xor_sync(0xffffffffu, s, o);
    if (lane == 0) g_scores[b * LL + l] = s * SCALE;
}

// -------- K2: row softmax; writes weights output (stride NBLK) --------
// grid BB, block 256
__global__ void k_softmax(float* __restrict__ out_w, int blk) {
    const int b = blockIdx.x;
    const int tid = threadIdx.x;
    __shared__ float red[256];

    float m = -1e30f;
    for (int l = tid; l < LL; l += 256) m = fmaxf(m, g_scores[b * LL + l]);
    red[tid] = m; __syncthreads();
    for (int o = 128; o > 0; o >>= 1) { if (tid < o) red[tid] = fmaxf(red[tid], red[tid + o]); __syncthreads(); }
    m = red[0]; __syncthreads();

    float sum = 0.f;
    for (int l = tid; l < LL; l += 256) {
        float e = __expf(g_scores[b * LL + l] - m);
        g_scores[b * LL + l] = e;
        sum += e;
    }
    red[tid] = sum; __syncthreads();
    for (int o = 128; o > 0; o >>= 1) { if (tid < o) red[tid] += red[tid + o]; __syncthreads(); }
    const float inv = 1.f / red[0];
    __syncthreads();

    for (int l = tid; l < LL; l += 256) {
        float s = g_scores[b * LL + l] * inv;
        g_scores[b * LL + l] = s;
        out_w[(size_t)(b * LL + l) * NBLK + blk] = s;
    }
}

// -------- K3: A[b,:] = sum_l s[b,l] * v[b,l,:]  (deterministic partials) --------
// grid (LSPLIT, BB), block 128 (each thread owns 4 d's via float4; full 512-d row per CTA)
__global__ void k_attnv(const float* __restrict__ v) {
    const int part = blockIdx.x, b = blockIdx.y;
    const int tid = threadIdx.x;
    __shared__ float ss[LCHUNK];
    ss[tid] = g_scores[b * LL + part * LCHUNK + tid];
    __syncthreads();

    const float4* __restrict__ v4 =
        (const float4*)(v + (size_t)b * LL * DD + (size_t)(part * LCHUNK) * DD);
    float4 acc = make_float4(0.f, 0.f, 0.f, 0.f);
#pragma unroll 4
    for (int l = 0; l < LCHUNK; l++) {
        const float s = ss[l];
        float4 vv = v4[(size_t)l * (DD / 4) + tid];
        acc.x += s * vv.x; acc.y += s * vv.y; acc.z += s * vv.z; acc.w += s * vv.w;
    }
    ((float4*)&g_Apart[part][b][0])[tid] = acc;
}

// -------- block reduce helper --------
__device__ __forceinline__ float block_sum(float val, float* red, int tid) {
    red[tid] = val; __syncthreads();
    for (int o = 128; o > 0; o >>= 1) { if (tid < o) red[tid] += red[tid + o]; __syncthreads(); }
    float r = red[0]; __syncthreads();
    return r;
}

// -------- K4: reduce partials, norm1, FFN, norm2, update q state, write out --------
// grid BB, block 256
__global__ void k_ffn(const float* __restrict__ W1, const float* __restrict__ b1,
                      const float* __restrict__ W2, const float* __restrict__ b2,
                      const float* __restrict__ a1, const float* __restrict__ bi1,
                      const float* __restrict__ a2, const float* __restrict__ bi2,
                      float* __restrict__ out, int blk) {
    const int b = blockIdx.x;
    const int tid = threadIdx.x;
    __shared__ float xq[DD];
    __shared__ float qn[DD];
    __shared__ float h[DFF];
    __shared__ float red[256];

    // reduce A partials + residual q
    for (int d = tid; d < DD; d += 256) {
        float a = 0.f;
#pragma unroll
        for (int p = 0; p < LSPLIT; p++) a += g_Apart[p][b][d];
        xq[d] = a + g_q[b * DD + d];
    }
    __syncthreads();

    // norm1 (ddof=1, alpha*(x-mu)/(std+eps)+bias)
    float ls = 0.f;
    for (int d = tid; d < DD; d += 256) ls += xq[d];
    const float mu1 = block_sum(ls, red, tid) * (1.f / DD);
    float lv = 0.f;
    for (int d = tid; d < DD; d += 256) { float t = xq[d] - mu1; lv += t * t; }
    const float var1 = block_sum(lv, red, tid) * (1.f / (DD - 1));
    const float inv1 = 1.f / (sqrtf(var1) + EPSN);
    for (int d = tid; d < DD; d += 256)
        qn[d] = a1[blk * DD + d] * (xq[d] - mu1) * inv1 + bi1[blk * DD + d];
    __syncthreads();

    // h = relu(qn @ W1 + b1)   (thread j owns column j; W1 row reads coalesced)
    {
        const int j = tid;
        float acc = b1[blk * DFF + j];
        const float* __restrict__ w1 = W1 + (size_t)blk * DD * DFF + j;
#pragma unroll 8
        for (int d = 0; d < DD; d++) acc += qn[d] * w1[(size_t)d * DFF];
        h[j] = fmaxf(acc, 0.f);
    }
    __syncthreads();

    // ff = h @ W2 + b2 ; y = qn + ff  (each thread owns d=tid and d=tid+256)
    {
        float f0 = b2[blk * DD + tid];
        float f1 = b2[blk * DD + tid + 256];
        const float* __restrict__ w2 = W2 + (size_t)blk * DFF * DD;
#pragma unroll 8
        for (int j = 0; j < DFF; j++) {
            const float hv = h[j];
            f0 += hv * w2[(size_t)j * DD + tid];
            f1 += hv * w2[(size_t)j * DD + tid + 256];
        }
        xq[tid]       = qn[tid] + f0;
        xq[tid + 256] = qn[tid + 256] + f1;
    }
    __syncthreads();

    // norm2
    float ls2 = 0.f;
    for (int d = tid; d < DD; d += 256) ls2 += xq[d];
    const float mu2 = block_sum(ls2, red, tid) * (1.f / DD);
    float lv2 = 0.f;
    for (int d = tid; d < DD; d += 256) { float t = xq[d] - mu2; lv2 += t * t; }
    const float var2 = block_sum(lv2, red, tid) * (1.f / (DD - 1));
    const float inv2 = 1.f / (sqrtf(var2) + EPSN);

    for (int d = tid; d < DD; d += 256) {
        const float r = a2[blk * DD + d] * (xq[d] - mu2) * inv2 + bi2[blk * DD + d];
        g_q[b * DD + d] = r;
        if (blk == 2) out[(size_t)b * 1024 + d] = r;           // head 0 output
        if (blk == 5) out[(size_t)b * 1024 + 512 + d] = r;     // head 1 output
    }
}

extern "C" void kernel_launch(void* const* d_in, const int* in_sizes, int n_in,
                              void* d_out, int out_size) {
    const float* q   = (const float*)d_in[0];
    const float* k   = (const float*)d_in[1];
    const float* v   = (const float*)d_in[2];
    const float* W1  = (const float*)d_in[3];
    const float* b1  = (const float*)d_in[4];
    const float* W2  = (const float*)d_in[5];
    const float* b2  = (const float*)d_in[6];
    const float* a1  = (const float*)d_in[7];
    const float* bi1 = (const float*)d_in[8];
    const float* a2  = (const float*)d_in[9];
    const float* bi2 = (const float*)d_in[10];

    float* out   = (float*)d_out;                 // (32, 1024)
    float* out_w = (float*)d_out + BB * 2 * DD;   // (32, 2048, 6)

    k_init_q<<<(BB * DD + 255) / 256, 256>>>(q);
    for (int blk = 0; blk < NBLK; blk++) {
        k_scores<<<dim3(LL / 8, BB), 256>>>(k);
        k_softmax<<<BB, 256>>>(out_w, blk);
        k_attnv<<<dim3(LSPLIT, BB), 128>>>(v);
        k_ffn<<<BB, 256>>>(W1, b1, W2, b2, a1, bi1, a2, bi2, out, blk);
    }
}

// round 2
// speedup vs baseline: 1.4235x; 1.4235x over previous
#include <cuda_runtime.h>
#include <cuda_fp16.h>
#include <math.h>

#define BB 32
#define LL 2048
#define DD 512
#define DFF 256
#define NBLK 6
#define EPSN 1e-6f
#define NCH 64            // score-stat chunks per batch (32 rows each)
#define LSPLIT 32         // attnv L-splits (64 rows each)
#define SCALE 0.04419417382415922f  // 1/sqrt(512)

// -------- device scratch (no allocations allowed) --------
__device__ __half2 g_kh2[(size_t)BB * LL * DD / 2];   // 64 MB fp16 k
__device__ __half2 g_vh2[(size_t)BB * LL * DD / 2];   // 64 MB fp16 v
__device__ float g_scores[BB * LL];                   // raw scaled scores
__device__ float g_m[BB][NCH];                        // per-chunk max
__device__ float g_z[BB][NCH];                        // per-chunk expsum
__device__ float g_Apart[LSPLIT][BB][DD];             // 2 MB deterministic partials
__device__ float g_q[BB * DD];                        // running q state

// -------- K0: fp32 -> fp16 conversion for k/v, plus q-state init --------
// grid (N/4/256, 2), block 256; y==0 -> k (+q init), y==1 -> v
__global__ void k_convert(const float* __restrict__ kin, const float* __restrict__ vin,
                          const float* __restrict__ qin) {
    const size_t i = (size_t)blockIdx.x * 256 + threadIdx.x;   // float4 index
    const float4 f = (blockIdx.y == 0) ? ((const float4*)kin)[i] : ((const float4*)vin)[i];
    __half2 h0 = __floats2half2_rn(f.x, f.y);
    __half2 h1 = __floats2half2_rn(f.z, f.w);
    uint2 u;
    u.x = *reinterpret_cast<unsigned int*>(&h0);
    u.y = *reinterpret_cast<unsigned int*>(&h1);
    if (blockIdx.y == 0) {
        ((uint2*)g_kh2)[i] = u;
        if (i < BB * DD / 4) ((float4*)g_q)[i] = ((const float4*)qin)[i];
    } else {
        ((uint2*)g_vh2)[i] = u;
    }
}

__device__ __forceinline__ float dot8(uint4 u, float4 qa, float4 qb) {
    __half2 h0 = *(__half2*)&u.x, h1 = *(__half2*)&u.y;
    __half2 h2 = *(__half2*)&u.z, h3 = *(__half2*)&u.w;
    float2 f0 = __half22float2(h0), f1 = __half22float2(h1);
    float2 f2 = __half22float2(h2), f3 = __half22float2(h3);
    return f0.x * qa.x + f0.y * qa.y + f1.x * qa.z + f1.y * qa.w +
           f2.x * qb.x + f2.y * qb.y + f3.x * qb.z + f3.y * qb.w;
}

// -------- K1: scores + per-chunk softmax stats --------
// grid (NCH, BB), block 256: 8 warps x 4 rows = 32 rows per CTA
__global__ void k_scores(int dummy) {
    const int b = blockIdx.y, tid = threadIdx.x;
    const int w = tid >> 5, lane = tid & 31;
    const int chunk = blockIdx.x;
    const int row0 = chunk * 32 + w * 4;

    // q slice for this lane held in registers (reused across 4 rows)
    const float4* q4 = (const float4*)(g_q + b * DD);
    const float4 qa = q4[2 * lane],        qb = q4[2 * lane + 1];
    const float4 qc = q4[2 * (lane + 32)], qd = q4[2 * (lane + 32) + 1];

    __shared__ float sc[32];
    float sr[4];
#pragma unroll
    for (int r = 0; r < 4; r++) {
        const uint4* kr = (const uint4*)((const __half*)g_kh2 +
                                         ((size_t)b * LL + row0 + r) * DD);
        uint4 u0 = kr[lane], u1 = kr[lane + 32];
        float s = dot8(u0, qa, qb) + dot8(u1, qc, qd);
#pragma unroll
        for (int o = 16; o > 0; o >>= 1) s += __shfl_xor_sync(0xffffffffu, s, o);
        sr[r] = s * SCALE;
    }
    if (lane < 4) {
        const float v = sr[lane];
        g_scores[b * LL + row0 + lane] = v;
        sc[w * 4 + lane] = v;
    }
    __syncthreads();

    if (tid < 32) {
        const float s = sc[tid];
        float m = s;
#pragma unroll
        for (int o = 16; o > 0; o >>= 1) m = fmaxf(m, __shfl_xor_sync(0xffffffffu, m, o));
        float e = __expf(s - m);
#pragma unroll
        for (int o = 16; o > 0; o >>= 1) e += __shfl_xor_sync(0xffffffffu, e, o);
        if (tid == 0) { g_m[b][chunk] = m; g_z[b][chunk] = e; }
    }
}

// -------- K2: combine stats, normalize, write weights, A partials --------
// grid (LSPLIT, BB), block 256; chunk = 64 rows, thread owns 4 d's
__global__ void k_attnv(float* __restrict__ out_w, int blk) {
    const int part = blockIdx.x, b = blockIdx.y;
    const int tid = threadIdx.x;
    __shared__ float se[64];
    __shared__ float s_m, s_inv;
    __shared__ float4 sacc[128];

    if (tid < 32) {
        const float m0 = g_m[b][tid], m1 = g_m[b][tid + 32];
        const float z0 = g_z[b][tid], z1 = g_z[b][tid + 32];
        float m = fmaxf(m0, m1);
#pragma unroll
        for (int o = 16; o > 0; o >>= 1) m = fmaxf(m, __shfl_xor_sync(0xffffffffu, m, o));
        float z = z0 * __expf(m0 - m) + z1 * __expf(m1 - m);
#pragma unroll
        for (int o = 16; o > 0; o >>= 1) z += __shfl_xor_sync(0xffffffffu, z, o);
        if (tid == 0) { s_m = m; s_inv = 1.f / z; }
    }
    __syncthreads();
    if (tid < 64) {
        const int l = part * 64 + tid;
        const float e = __expf(g_scores[b * LL + l] - s_m) * s_inv;
        se[tid] = e;
        out_w[(size_t)(b * LL + l) * NBLK + blk] = e;
    }
    __syncthreads();

    const int dl = tid & 127;           // d-lane: owns d [4*dl, 4*dl+4)
    const int rbase = tid >> 7;         // 0 or 1: even/odd rows
    const __half* vb = (const __half*)g_vh2 + ((size_t)b * LL + part * 64) * DD;
    float4 acc = make_float4(0.f, 0.f, 0.f, 0.f);
#pragma unroll 8
    for (int l = rbase; l < 64; l += 2) {
        uint2 u = ((const uint2*)(vb + (size_t)l * DD))[dl];
        __half2 h0 = *(__half2*)&u.x, h1 = *(__half2*)&u.y;
        float2 f0 = __half22float2(h0), f1 = __half22float2(h1);
        const float e = se[l];
        acc.x += e * f0.x; acc.y += e * f0.y; acc.z += e * f1.x; acc.w += e * f1.y;
    }
    if (tid >= 128) sacc[dl] = acc;
    __syncthreads();
    if (tid < 128) {
        const float4 o = sacc[dl];
        acc.x += o.x; acc.y += o.y; acc.z += o.z; acc.w += o.w;
        ((float4*)&g_Apart[part][b][0])[dl] = acc;
    }
}

// -------- block reduce over 512 threads --------
__device__ __forceinline__ float block_sum512(float val, float* red, int tid) {
    red[tid] = val; __syncthreads();
#pragma unroll
    for (int o = 256; o > 0; o >>= 1) {
        if (tid < o) red[tid] += red[tid + o];
        __syncthreads();
    }
    const float r = red[0]; __syncthreads();
    return r;
}

// -------- K3: partial reduce, norm1, FFN, norm2, q update, out write --------
// grid BB, block 512
__global__ void k_ffn(const float* __restrict__ W1, const float* __restrict__ b1,
                      const float* __restrict__ W2, const float* __restrict__ b2,
                      const float* __restrict__ a1, const float* __restrict__ bi1,
                      const float* __restrict__ a2, const float* __restrict__ bi2,
                      float* __restrict__ out, int blk) {
    const int b = blockIdx.x;
    const int tid = threadIdx.x;
    __shared__ float qn[DD];
    __shared__ float h[DFF];
    __shared__ float hp[512];
    __shared__ float red[512];

    // reduce A partials + residual q (thread owns d = tid)
    float a = 0.f;
#pragma unroll
    for (int p = 0; p < LSPLIT; p++) a += g_Apart[p][b][tid];
    const float x = a + g_q[b * DD + tid];

    // norm1 (ddof=1)
    const float mu1 = block_sum512(x, red, tid) * (1.f / DD);
    const float t1 = x - mu1;
    const float var1 = block_sum512(t1 * t1, red, tid) * (1.f / (DD - 1));
    const float inv1 = 1.f / (sqrtf(var1) + EPSN);
    const float qv = a1[blk * DD + tid] * t1 * inv1 + bi1[blk * DD + tid];
    qn[tid] = qv;
    __syncthreads();

    // h = relu(qn @ W1 + b1): 2 threads per column, split over d
    {
        const int j = tid & 255, half = tid >> 8;
        float acc = 0.f;
        const float* __restrict__ w1 = W1 + (size_t)blk * DD * DFF + (size_t)half * 256 * DFF + j;
        const float* __restrict__ qh = qn + half * 256;
#pragma unroll 8
        for (int d = 0; d < 256; d++) acc += qh[d] * w1[(size_t)d * DFF];
        hp[tid] = acc;
    }
    __syncthreads();
    if (tid < DFF) h[tid] = fmaxf(hp[tid] + hp[tid + 256] + b1[blk * DFF + tid], 0.f);
    __syncthreads();

    // ff = h @ W2 + b2 ; y = qn + ff (thread owns output d = tid)
    float f = b2[blk * DD + tid];
    {
        const float* __restrict__ w2 = W2 + (size_t)blk * DFF * DD;
#pragma unroll 8
        for (int j = 0; j < DFF; j++) f += h[j] * w2[(size_t)j * DD + tid];
    }
    const float y = qv + f;

    // norm2
    const float mu2 = block_sum512(y, red, tid) * (1.f / DD);
    const float t2 = y - mu2;
    const float var2 = block_sum512(t2 * t2, red, tid) * (1.f / (DD - 1));
    const float inv2 = 1.f / (sqrtf(var2) + EPSN);
    const float r = a2[blk * DD + tid] * t2 * inv2 + bi2[blk * DD + tid];
    g_q[b * DD + tid] = r;
    if (blk == 2) out[(size_t)b * 1024 + tid] = r;
    if (blk == 5) out[(size_t)b * 1024 + 512 + tid] = r;
}

extern "C" void kernel_launch(void* const* d_in, const int* in_sizes, int n_in,
                              void* d_out, int out_size) {
    const float* q   = (const float*)d_in[0];
    const float* k   = (const float*)d_in[1];
    const float* v   = (const float*)d_in[2];
    const float* W1  = (const float*)d_in[3];
    const float* b1  = (const float*)d_in[4];
    const float* W2  = (const float*)d_in[5];
    const float* b2  = (const float*)d_in[6];
    const float* a1  = (const float*)d_in[7];
    const float* bi1 = (const float*)d_in[8];
    const float* a2  = (const float*)d_in[9];
    const float* bi2 = (const float*)d_in[10];

    float* out   = (float*)d_out;                 // (32, 1024)
    float* out_w = (float*)d_out + BB * 2 * DD;   // (32, 2048, 6)

    const int n4 = BB * LL * DD / 4;              // float4 count per tensor
    k_convert<<<dim3(n4 / 256, 2), 256>>>(k, v, q);
    for (int blk = 0; blk < NBLK; blk++) {
        k_scores<<<dim3(NCH, BB), 256>>>(0);
        k_attnv<<<dim3(LSPLIT, BB), 256>>>(out_w, blk);
        k_ffn<<<BB, 512>>>(W1, b1, W2, b2, a1, bi1, a2, bi2, out, blk);
    }
}

// round 3
// speedup vs baseline: 1.8643x; 1.3097x over previous
#include <cuda_runtime.h>
#include <cuda_fp16.h>
#include <math.h>

#define BB 32
#define LL 2048
#define DD 512
#define DFF 256
#define NBLK 6
#define EPSN 1e-6f
#define NCH 64            // score-stat chunks per batch (32 rows each)
#define LSPLIT 32         // attnv L-splits (64 rows each)
#define SCALE 0.04419417382415922f  // 1/sqrt(512)

// -------- device scratch (no allocations allowed) --------
__device__ __half2 g_kh2[(size_t)BB * LL * DD / 2];   // 64 MB fp16 k
__device__ __half2 g_vh2[(size_t)BB * LL * DD / 2];   // 64 MB fp16 v
__device__ float g_scores[BB * LL];                   // raw scaled scores
__device__ float g_m[BB][NCH];                        // per-chunk max
__device__ float g_z[BB][NCH];                        // per-chunk expsum
__device__ float g_Apart[LSPLIT][BB][DD];             // 2 MB deterministic partials
__device__ float g_q[BB * DD];                        // running q state

// -------- K0: fp32 -> fp16 conversion for k/v, plus q-state init --------
__global__ void k_convert(const float* __restrict__ kin, const float* __restrict__ vin,
                          const float* __restrict__ qin) {
    const size_t i = (size_t)blockIdx.x * 256 + threadIdx.x;   // float4 index
    const float4 f = (blockIdx.y == 0) ? ((const float4*)kin)[i] : ((const float4*)vin)[i];
    __half2 h0 = __floats2half2_rn(f.x, f.y);
    __half2 h1 = __floats2half2_rn(f.z, f.w);
    uint2 u;
    u.x = *reinterpret_cast<unsigned int*>(&h0);
    u.y = *reinterpret_cast<unsigned int*>(&h1);
    if (blockIdx.y == 0) {
        ((uint2*)g_kh2)[i] = u;
        if (i < BB * DD / 4) ((float4*)g_q)[i] = ((const float4*)qin)[i];
    } else {
        ((uint2*)g_vh2)[i] = u;
    }
}

__device__ __forceinline__ float dot8(uint4 u, float4 qa, float4 qb) {
    __half2 h0 = *(__half2*)&u.x, h1 = *(__half2*)&u.y;
    __half2 h2 = *(__half2*)&u.z, h3 = *(__half2*)&u.w;
    float2 f0 = __half22float2(h0), f1 = __half22float2(h1);
    float2 f2 = __half22float2(h2), f3 = __half22float2(h3);
    return f0.x * qa.x + f0.y * qa.y + f1.x * qa.z + f1.y * qa.w +
           f2.x * qb.x + f2.y * qb.y + f3.x * qb.z + f3.y * qb.w;
}

// -------- K1: scores + per-chunk softmax stats --------
// grid (NCH, BB), block 256: 8 warps x 4 rows; all loads issued before reduces
__global__ void k_scores(int dummy) {
    const int b = blockIdx.y, tid = threadIdx.x;
    const int w = tid >> 5, lane = tid & 31;
    const int chunk = blockIdx.x;
    const int row0 = chunk * 32 + w * 4;

    const float4* q4 = (const float4*)(g_q + b * DD);
    const float4 qa = q4[2 * lane],        qb = q4[2 * lane + 1];
    const float4 qc = q4[2 * (lane + 32)], qd = q4[2 * (lane + 32) + 1];

    __shared__ float sc[32];
    uint4 u0[4], u1[4];
#pragma unroll
    for (int r = 0; r < 4; r++) {
        const uint4* kr = (const uint4*)((const __half*)g_kh2 +
                                         ((size_t)b * LL + row0 + r) * DD);
        u0[r] = kr[lane];
        u1[r] = kr[lane + 32];
    }
    float sr[4];
#pragma unroll
    for (int r = 0; r < 4; r++) {
        float s = dot8(u0[r], qa, qb) + dot8(u1[r], qc, qd);
#pragma unroll
        for (int o = 16; o > 0; o >>= 1) s += __shfl_xor_sync(0xffffffffu, s, o);
        sr[r] = s * SCALE;
    }
    if (lane < 4) {
        const float v = sr[lane];
        g_scores[b * LL + row0 + lane] = v;
        sc[w * 4 + lane] = v;
    }
    __syncthreads();

    if (tid < 32) {
        const float s = sc[tid];
        float m = s;
#pragma unroll
        for (int o = 16; o > 0; o >>= 1) m = fmaxf(m, __shfl_xor_sync(0xffffffffu, m, o));
        float e = __expf(s - m);
#pragma unroll
        for (int o = 16; o > 0; o >>= 1) e += __shfl_xor_sync(0xffffffffu, e, o);
        if (tid == 0) { g_m[b][chunk] = m; g_z[b][chunk] = e; }
    }
}

// -------- K2: combine stats, normalize, write weights, A partials --------
// grid (LSPLIT, BB), block 256; 64 rows; thread owns 8 d's (uint4), 4-way row split
__global__ void k_attnv(float* __restrict__ out_w, int blk) {
    const int part = blockIdx.x, b = blockIdx.y;
    const int tid = threadIdx.x;
    __shared__ float se[64];
    __shared__ float s_m, s_inv;
    __shared__ float sacc[4][DD];   // 8 KB partials

    if (tid < 32) {
        const float m0 = g_m[b][tid], m1 = g_m[b][tid + 32];
        const float z0 = g_z[b][tid], z1 = g_z[b][tid + 32];
        float m = fmaxf(m0, m1);
#pragma unroll
        for (int o = 16; o > 0; o >>= 1) m = fmaxf(m, __shfl_xor_sync(0xffffffffu, m, o));
        float z = z0 * __expf(m0 - m) + z1 * __expf(m1 - m);
#pragma unroll
        for (int o = 16; o > 0; o >>= 1) z += __shfl_xor_sync(0xffffffffu, z, o);
        if (tid == 0) { s_m = m; s_inv = 1.f / z; }
    }
    __syncthreads();
    if (tid < 64) {
        const int l = part * 64 + tid;
        const float e = __expf(g_scores[b * LL + l] - s_m) * s_inv;
        se[tid] = e;
        out_w[(size_t)(b * LL + l) * NBLK + blk] = e;
    }
    __syncthreads();

    const int dl = tid & 63;            // owns d [8*dl, 8*dl+8)
    const int rg = tid >> 6;            // row group 0..3
    const __half* vb = (const __half*)g_vh2 + ((size_t)b * LL + part * 64) * DD;
    float acc[8] = {0.f, 0.f, 0.f, 0.f, 0.f, 0.f, 0.f, 0.f};
#pragma unroll
    for (int l = rg; l < 64; l += 4) {
        uint4 u = ((const uint4*)(vb + (size_t)l * DD))[dl];
        const float e = se[l];
        __half2 h0 = *(__half2*)&u.x, h1 = *(__half2*)&u.y;
        __half2 h2 = *(__half2*)&u.z, h3 = *(__half2*)&u.w;
        float2 f0 = __half22float2(h0), f1 = __half22float2(h1);
        float2 f2 = __half22float2(h2), f3 = __half22float2(h3);
        acc[0] += e * f0.x; acc[1] += e * f0.y; acc[2] += e * f1.x; acc[3] += e * f1.y;
        acc[4] += e * f2.x; acc[5] += e * f2.y; acc[6] += e * f3.x; acc[7] += e * f3.y;
    }
#pragma unroll
    for (int c = 0; c < 8; c++) sacc[rg][dl * 8 + c] = acc[c];
    __syncthreads();
    // 256 threads each reduce 2 output d's
#pragma unroll
    for (int rep = 0; rep < 2; rep++) {
        const int d = tid + rep * 256;
        g_Apart[part][b][d] = sacc[0][d] + sacc[1][d] + sacc[2][d] + sacc[3][d];
    }
}

// -------- shuffle block reduce over 512 threads (16 warps) --------
__device__ __forceinline__ float block_sum512(float val, float* red, int tid) {
#pragma unroll
    for (int o = 16; o > 0; o >>= 1) val += __shfl_xor_sync(0xffffffffu, val, o);
    if ((tid & 31) == 0) red[tid >> 5] = val;
    __syncthreads();
    if (tid < 32) {
        float v = (tid < 16) ? red[tid] : 0.f;
#pragma unroll
        for (int o = 8; o > 0; o >>= 1) v += __shfl_xor_sync(0xffffffffu, v, o);
        if (tid == 0) red[0] = v;
    }
    __syncthreads();
    const float r = red[0];
    __syncthreads();
    return r;
}

// -------- K3: partial reduce, norm1, FFN (float4 split-K), norm2 --------
// grid BB, block 512
__global__ void k_ffn(const float* __restrict__ W1, const float* __restrict__ b1,
                      const float* __restrict__ W2, const float* __restrict__ b2,
                      const float* __restrict__ a1, const float* __restrict__ bi1,
                      const float* __restrict__ a2, const float* __restrict__ bi2,
                      float* __restrict__ out, int blk) {
    const int b = blockIdx.x;
    const int tid = threadIdx.x;
    __shared__ float qn[DD];
    __shared__ float h[DFF];
    __shared__ float hp[8 * DFF];   // 8 KB W1 partials
    __shared__ float fp[4 * DD];    // 8 KB W2 partials
    __shared__ float red[32];

    // reduce A partials + residual q (thread owns d = tid)
    float a = 0.f;
#pragma unroll
    for (int p = 0; p < LSPLIT; p++) a += g_Apart[p][b][tid];
    const float x = a + g_q[b * DD + tid];

    // norm1 (ddof=1)
    const float mu1 = block_sum512(x, red, tid) * (1.f / DD);
    const float t1 = x - mu1;
    const float var1 = block_sum512(t1 * t1, red, tid) * (1.f / (DD - 1));
    const float inv1 = 1.f / (sqrtf(var1) + EPSN);
    const float qv = a1[blk * DD + tid] * t1 * inv1 + bi1[blk * DD + tid];
    qn[tid] = qv;
    __syncthreads();

    // h = relu(qn @ W1 + b1): 8-way d-split, thread owns 4 j's (float4)
    {
        const int j4 = tid & 63, ds = tid >> 6;
        const float4* __restrict__ w1 =
            (const float4*)(W1 + (size_t)blk * DD * DFF) + (size_t)ds * 64 * (DFF / 4) + j4;
        const float* __restrict__ qh = qn + ds * 64;
        float4 acc = make_float4(0.f, 0.f, 0.f, 0.f);
#pragma unroll 16
        for (int d = 0; d < 64; d++) {
            const float4 wv = w1[(size_t)d * (DFF / 4)];
            const float qd = qh[d];
            acc.x += qd * wv.x; acc.y += qd * wv.y; acc.z += qd * wv.z; acc.w += qd * wv.w;
        }
        ((float4*)hp)[tid] = acc;   // hp[ds*256 + j]
    }
    __syncthreads();
    if (tid < DFF) {
        float s = b1[blk * DFF + tid];
#pragma unroll
        for (int ds = 0; ds < 8; ds++) s += hp[ds * DFF + tid];
        h[tid] = fmaxf(s, 0.f);
    }
    __syncthreads();

    // ff = h @ W2 + b2: 4-way j-split, thread owns 4 d's (float4)
    {
        const int d4 = tid & 127, js = tid >> 7;
        const float4* __restrict__ w2 =
            (const float4*)(W2 + (size_t)blk * DFF * DD) + (size_t)js * 64 * (DD / 4) + d4;
        const float* __restrict__ hh = h + js * 64;
        float4 acc = make_float4(0.f, 0.f, 0.f, 0.f);
#pragma unroll 16
        for (int j = 0; j < 64; j++) {
            const float4 wv = w2[(size_t)j * (DD / 4)];
            const float hv = hh[j];
            acc.x += hv * wv.x; acc.y += hv * wv.y; acc.z += hv * wv.z; acc.w += hv * wv.w;
        }
        ((float4*)fp)[tid] = acc;   // fp[js*512 + d]
    }
    __syncthreads();
    float f = b2[blk * DD + tid];
#pragma unroll
    for (int js = 0; js < 4; js++) f += fp[js * DD + tid];
    const float y = qv + f;

    // norm2
    const float mu2 = block_sum512(y, red, tid) * (1.f / DD);
    const float t2 = y - mu2;
    const float var2 = block_sum512(t2 * t2, red, tid) * (1.f / (DD - 1));
    const float inv2 = 1.f / (sqrtf(var2) + EPSN);
    const float r = a2[blk * DD + tid] * t2 * inv2 + bi2[blk * DD + tid];
    g_q[b * DD + tid] = r;
    if (blk == 2) out[(size_t)b * 1024 + tid] = r;
    if (blk == 5) out[(size_t)b * 1024 + 512 + tid] = r;
}

extern "C" void kernel_launch(void* const* d_in, const int* in_sizes, int n_in,
                              void* d_out, int out_size) {
    const float* q   = (const float*)d_in[0];
    const float* k   = (const float*)d_in[1];
    const float* v   = (const float*)d_in[2];
    const float* W1  = (const float*)d_in[3];
    const float* b1  = (const float*)d_in[4];
    const float* W2  = (const float*)d_in[5];
    const float* b2  = (const float*)d_in[6];
    const float* a1  = (const float*)d_in[7];
    const float* bi1 = (const float*)d_in[8];
    const float* a2  = (const float*)d_in[9];
    const float* bi2 = (const float*)d_in[10];

    float* out   = (float*)d_out;                 // (32, 1024)
    float* out_w = (float*)d_out + BB * 2 * DD;   // (32, 2048, 6)

    const int n4 = BB * LL * DD / 4;              // float4 count per tensor
    k_convert<<<dim3(n4 / 256, 2), 256>>>(k, v, q);
    for (int blk = 0; blk < NBLK; blk++) {
        k_scores<<<dim3(NCH, BB), 256>>>(0);
        k_attnv<<<dim3(LSPLIT, BB), 256>>>(out_w, blk);
        k_ffn<<<BB, 512>>>(W1, b1, W2, b2, a1, bi1, a2, bi2, out, blk);
    }
}

// round 4
// speedup vs baseline: 1.9692x; 1.0563x over previous
#include <cuda_runtime.h>
#include <cuda_fp16.h>
#include <math.h>

#define BB 32
#define LL 2048
#define DD 512
#define DFF 256
#define NBLK 6
#define EPSN 1e-6f
#define NCH 64            // score-stat chunks per batch (32 rows each)
#define LSPLIT 32         // attnv L-splits (64 rows each)
#define SCALE 0.04419417382415922f  // 1/sqrt(512)

// -------- device scratch (no allocations allowed) --------
__device__ __half2 g_kh2[(size_t)BB * LL * DD / 2];   // 64 MB fp16 k
__device__ __half2 g_vh2[(size_t)BB * LL * DD / 2];   // 64 MB fp16 v
__device__ float g_scores[BB * LL];
__device__ float g_m[BB][NCH];
__device__ float g_z[BB][NCH];
__device__ float g_Apart[LSPLIT][BB][DD];             // 2 MB deterministic partials
__device__ float g_q[BB * DD];                        // running q state
__device__ float g_qn[BB * DD];                       // post-norm1 q
__device__ float g_h[BB * DFF];                       // FFN hidden
__device__ float g_y[BB * DD];                        // pre-norm2

__device__ __forceinline__ unsigned int pack2(float a, float b) {
    __half2 h = __floats2half2_rn(a, b);
    return *reinterpret_cast<unsigned int*>(&h);
}

__device__ __forceinline__ float dot8h(uint4 u, float4 qa, float4 qb) {
    __half2 h0 = *(__half2*)&u.x, h1 = *(__half2*)&u.y;
    __half2 h2 = *(__half2*)&u.z, h3 = *(__half2*)&u.w;
    float2 f0 = __half22float2(h0), f1 = __half22float2(h1);
    float2 f2 = __half22float2(h2), f3 = __half22float2(h3);
    return f0.x * qa.x + f0.y * qa.y + f1.x * qa.z + f1.y * qa.w +
           f2.x * qb.x + f2.y * qb.y + f3.x * qb.z + f3.y * qb.w;
}

// -------- K1: scores + per-chunk stats; blk0 also converts k fp32->fp16 --------
// grid (NCH, BB), block 256: 8 warps x 4 rows
__global__ void k_scores(const float* __restrict__ kin, const float* __restrict__ qin, int blk) {
    const int b = blockIdx.y, tid = threadIdx.x;
    const int w = tid >> 5, lane = tid & 31;
    const int chunk = blockIdx.x;
    const int row0 = chunk * 32 + w * 4;

    const float* qsrc = (blk == 0) ? (qin + b * DD) : (g_q + b * DD);
    const float4* q4 = (const float4*)qsrc;
    const float4 qa = q4[2 * lane],        qb = q4[2 * lane + 1];
    const float4 qc = q4[2 * (lane + 32)], qd = q4[2 * (lane + 32) + 1];

    __shared__ float sc[32];
    float sr[4];

    if (blk == 0) {
#pragma unroll
        for (int r = 0; r < 4; r++) {
            const float4* kr = (const float4*)(kin + ((size_t)b * LL + row0 + r) * DD);
            float4 a0 = kr[2 * lane], a1 = kr[2 * lane + 1];
            float4 a2 = kr[2 * lane + 64], a3 = kr[2 * lane + 65];
            uint4* kw = (uint4*)((__half*)g_kh2 + ((size_t)b * LL + row0 + r) * DD);
            uint4 p0, p1;
            p0.x = pack2(a0.x, a0.y); p0.y = pack2(a0.z, a0.w);
            p0.z = pack2(a1.x, a1.y); p0.w = pack2(a1.z, a1.w);
            p1.x = pack2(a2.x, a2.y); p1.y = pack2(a2.z, a2.w);
            p1.z = pack2(a3.x, a3.y); p1.w = pack2(a3.z, a3.w);
            kw[lane] = p0; kw[lane + 32] = p1;
            float s = a0.x * qa.x + a0.y * qa.y + a0.z * qa.z + a0.w * qa.w
                    + a1.x * qb.x + a1.y * qb.y + a1.z * qb.z + a1.w * qb.w
                    + a2.x * qc.x + a2.y * qc.y + a2.z * qc.z + a2.w * qc.w
                    + a3.x * qd.x + a3.y * qd.y + a3.z * qd.z + a3.w * qd.w;
#pragma unroll
            for (int o = 16; o > 0; o >>= 1) s += __shfl_xor_sync(0xffffffffu, s, o);
            sr[r] = s * SCALE;
        }
    } else {
        uint4 u0[4], u1[4];
#pragma unroll
        for (int r = 0; r < 4; r++) {
            const uint4* kr = (const uint4*)((const __half*)g_kh2 +
                                             ((size_t)b * LL + row0 + r) * DD);
            u0[r] = kr[lane];
            u1[r] = kr[lane + 32];
        }
#pragma unroll
        for (int r = 0; r < 4; r++) {
            float s = dot8h(u0[r], qa, qb) + dot8h(u1[r], qc, qd);
#pragma unroll
            for (int o = 16; o > 0; o >>= 1) s += __shfl_xor_sync(0xffffffffu, s, o);
            sr[r] = s * SCALE;
        }
    }
    if (lane < 4) {
        const float v = sr[lane];
        g_scores[b * LL + row0 + lane] = v;
        sc[w * 4 + lane] = v;
    }
    __syncthreads();

    if (tid < 32) {
        const float s = sc[tid];
        float m = s;
#pragma unroll
        for (int o = 16; o > 0; o >>= 1) m = fmaxf(m, __shfl_xor_sync(0xffffffffu, m, o));
        float e = __expf(s - m);
#pragma unroll
        for (int o = 16; o > 0; o >>= 1) e += __shfl_xor_sync(0xffffffffu, e, o);
        if (tid == 0) { g_m[b][chunk] = m; g_z[b][chunk] = e; }
    }
}

// -------- K2: softmax finalize + weights out + A partials; blk0 converts v --------
// grid (LSPLIT, BB), block 256; thread owns 8 d's, 4-way row split
__global__ void k_attnv(const float* __restrict__ vin, float* __restrict__ out_w, int blk) {
    const int part = blockIdx.x, b = blockIdx.y;
    const int tid = threadIdx.x;
    __shared__ float se[64];
    __shared__ float s_m, s_inv;
    __shared__ float sacc[4][DD];

    if (tid < 32) {
        const float m0 = g_m[b][tid], m1 = g_m[b][tid + 32];
        const float z0 = g_z[b][tid], z1 = g_z[b][tid + 32];
        float m = fmaxf(m0, m1);
#pragma unroll
        for (int o = 16; o > 0; o >>= 1) m = fmaxf(m, __shfl_xor_sync(0xffffffffu, m, o));
        float z = z0 * __expf(m0 - m) + z1 * __expf(m1 - m);
#pragma unroll
        for (int o = 16; o > 0; o >>= 1) z += __shfl_xor_sync(0xffffffffu, z, o);
        if (tid == 0) { s_m = m; s_inv = 1.f / z; }
    }
    __syncthreads();
    if (tid < 64) {
        const int l = part * 64 + tid;
        const float e = __expf(g_scores[b * LL + l] - s_m) * s_inv;
        se[tid] = e;
        out_w[(size_t)(b * LL + l) * NBLK + blk] = e;
    }
    __syncthreads();

    const int dl = tid & 63;
    const int rg = tid >> 6;
    float acc[8] = {0.f, 0.f, 0.f, 0.f, 0.f, 0.f, 0.f, 0.f};

    if (blk == 0) {
#pragma unroll
        for (int l = rg; l < 64; l += 4) {
            const float4* vr = (const float4*)(vin + ((size_t)b * LL + part * 64 + l) * DD);
            float4 c0 = vr[2 * dl], c1 = vr[2 * dl + 1];
            uint4 p;
            p.x = pack2(c0.x, c0.y); p.y = pack2(c0.z, c0.w);
            p.z = pack2(c1.x, c1.y); p.w = pack2(c1.z, c1.w);
            ((uint4*)((__half*)g_vh2 + ((size_t)b * LL + part * 64 + l) * DD))[dl] = p;
            const float e = se[l];
            acc[0] += e * c0.x; acc[1] += e * c0.y; acc[2] += e * c0.z; acc[3] += e * c0.w;
            acc[4] += e * c1.x; acc[5] += e * c1.y; acc[6] += e * c1.z; acc[7] += e * c1.w;
        }
    } else {
        const __half* vb = (const __half*)g_vh2 + ((size_t)b * LL + part * 64) * DD;
#pragma unroll
        for (int l = rg; l < 64; l += 4) {
            uint4 u = ((const uint4*)(vb + (size_t)l * DD))[dl];
            const float e = se[l];
            __half2 h0 = *(__half2*)&u.x, h1 = *(__half2*)&u.y;
            __half2 h2 = *(__half2*)&u.z, h3 = *(__half2*)&u.w;
            float2 f0 = __half22float2(h0), f1 = __half22float2(h1);
            float2 f2 = __half22float2(h2), f3 = __half22float2(h3);
            acc[0] += e * f0.x; acc[1] += e * f0.y; acc[2] += e * f1.x; acc[3] += e * f1.y;
            acc[4] += e * f2.x; acc[5] += e * f2.y; acc[6] += e * f3.x; acc[7] += e * f3.y;
        }
    }
#pragma unroll
    for (int c = 0; c < 8; c++) sacc[rg][dl * 8 + c] = acc[c];
    __syncthreads();
#pragma unroll
    for (int rep = 0; rep < 2; rep++) {
        const int d = tid + rep * 256;
        g_Apart[part][b][d] = sacc[0][d] + sacc[1][d] + sacc[2][d] + sacc[3][d];
    }
}

// -------- shuffle block reduce over 256 threads (8 warps) --------
__device__ __forceinline__ float block_sum256(float val, float* red, int tid) {
#pragma unroll
    for (int o = 16; o > 0; o >>= 1) val += __shfl_xor_sync(0xffffffffu, val, o);
    if ((tid & 31) == 0) red[tid >> 5] = val;
    __syncthreads();
    if (tid < 32) {
        float v = (tid < 8) ? red[tid] : 0.f;
#pragma unroll
        for (int o = 4; o > 0; o >>= 1) v += __shfl_xor_sync(0xffffffffu, v, o);
        if (tid == 0) red[0] = v;
    }
    __syncthreads();
    const float r = red[0];
    __syncthreads();
    return r;
}

// -------- K3a: Apart reduce + norm1 + W1 GEMM slice --------
// grid (4, BB), block 256; CTA (jc, b) owns 64 h-columns [64*jc, ...)
__global__ void k_nf1(const float* __restrict__ W1, const float* __restrict__ b1,
                      const float* __restrict__ a1, const float* __restrict__ bi1,
                      const float* __restrict__ qin, int blk) {
    const int jc = blockIdx.x, b = blockIdx.y;
    const int tid = threadIdx.x;
    __shared__ float qn_s[DD];
    __shared__ float hp[256];
    __shared__ float red[32];

    // x = sum_p Apart + residual (thread owns d = tid, tid+256)
    const float* res = (blk == 0) ? (qin + b * DD) : (g_q + b * DD);
    float xa = res[tid], xb = res[tid + 256];
#pragma unroll
    for (int p = 0; p < LSPLIT; p++) {
        xa += g_Apart[p][b][tid];
        xb += g_Apart[p][b][tid + 256];
    }

    // norm1 (ddof=1)
    const float mu = block_sum256(xa + xb, red, tid) * (1.f / DD);
    const float ta = xa - mu, tb = xb - mu;
    const float var = block_sum256(ta * ta + tb * tb, red, tid) * (1.f / (DD - 1));
    const float inv = 1.f / (sqrtf(var) + EPSN);
    const float qva = a1[blk * DD + tid] * ta * inv + bi1[blk * DD + tid];
    const float qvb = a1[blk * DD + tid + 256] * tb * inv + bi1[blk * DD + tid + 256];
    qn_s[tid] = qva; qn_s[tid + 256] = qvb;
    if (jc == 0) { g_qn[b * DD + tid] = qva; g_qn[b * DD + tid + 256] = qvb; }
    __syncthreads();

    // h-partial: thread (j = tid&63, ds = tid>>6) sums d in [128*ds, 128*ds+128)
    {
        const int j = tid & 63, ds = tid >> 6;
        const int jg = jc * 64 + j;
        const float* __restrict__ w1 = W1 + ((size_t)blk * DD + ds * 128) * DFF + jg;
        const float* __restrict__ qh = qn_s + ds * 128;
        float acc = 0.f;
#pragma unroll 8
        for (int d = 0; d < 128; d++) acc += qh[d] * w1[(size_t)d * DFF];
        hp[ds * 64 + j] = acc;
    }
    __syncthreads();
    if (tid < 64) {
        const int jg = jc * 64 + tid;
        const float s = hp[tid] + hp[64 + tid] + hp[128 + tid] + hp[192 + tid] + b1[blk * DFF + jg];
        g_h[b * DFF + jg] = fmaxf(s, 0.f);
    }
}

// -------- K3b: W2 GEMM slice + residual -> y --------
// grid (4, BB), block 256; CTA (dc, b) owns 128 d's [128*dc, ...)
__global__ void k_f2(const float* __restrict__ W2, const float* __restrict__ b2, int blk) {
    const int dc = blockIdx.x, b = blockIdx.y;
    const int tid = threadIdx.x;
    __shared__ float h_s[DFF];
    __shared__ float fp[256];

    h_s[tid] = g_h[b * DFF + tid];
    __syncthreads();

    // thread (d = tid&127, js = tid>>7) sums j in [128*js, 128*js+128)
    {
        const int d = tid & 127, js = tid >> 7;
        const int dg = dc * 128 + d;
        const float* __restrict__ w2 = W2 + ((size_t)blk * DFF + js * 128) * DD + dg;
        const float* __restrict__ hh = h_s + js * 128;
        float acc = 0.f;
#pragma unroll 8
        for (int j = 0; j < 128; j++) acc += hh[j] * w2[(size_t)j * DD];
        fp[js * 128 + d] = acc;
    }
    __syncthreads();
    if (tid < 128) {
        const int dg = dc * 128 + tid;
        g_y[b * DD + dg] = g_qn[b * DD + dg] + fp[tid] + fp[128 + tid] + b2[blk * DD + dg];
    }
}

// -------- shuffle block reduce over 512 threads --------
__device__ __forceinline__ float block_sum512(float val, float* red, int tid) {
#pragma unroll
    for (int o = 16; o > 0; o >>= 1) val += __shfl_xor_sync(0xffffffffu, val, o);
    if ((tid & 31) == 0) red[tid >> 5] = val;
    __syncthreads();
    if (tid < 32) {
        float v = (tid < 16) ? red[tid] : 0.f;
#pragma unroll
        for (int o = 8; o > 0; o >>= 1) v += __shfl_xor_sync(0xffffffffu, v, o);
        if (tid == 0) red[0] = v;
    }
    __syncthreads();
    const float r = red[0];
    __syncthreads();
    return r;
}

// -------- K3c: norm2 + q update + out writes --------
// grid BB, block 512
__global__ void k_n2(const float* __restrict__ a2, const float* __restrict__ bi2,
                     float* __restrict__ out, int blk) {
    const int b = blockIdx.x;
    const int tid = threadIdx.x;
    __shared__ float red[32];

    const float y = g_y[b * DD + tid];
    const float mu = block_sum512(y, red, tid) * (1.f / DD);
    const float t = y - mu;
    const float var = block_sum512(t * t, red, tid) * (1.f / (DD - 1));
    const float inv = 1.f / (sqrtf(var) + EPSN);
    const float r = a2[blk * DD + tid] * t * inv + bi2[blk * DD + tid];
    g_q[b * DD + tid] = r;
    if (blk == 2) out[(size_t)b * 1024 + tid] = r;
    if (blk == 5) out[(size_t)b * 1024 + 512 + tid] = r;
}

extern "C" void kernel_launch(void* const* d_in, const int* in_sizes, int n_in,
                              void* d_out, int out_size) {
    const float* q   = (const float*)d_in[0];
    const float* k   = (const float*)d_in[1];
    const float* v   = (const float*)d_in[2];
    const float* W1  = (const float*)d_in[3];
    const float* b1  = (const float*)d_in[4];
    const float* W2  = (const float*)d_in[5];
    const float* b2  = (const float*)d_in[6];
    const float* a1  = (const float*)d_in[7];
    const float* bi1 = (const float*)d_in[8];
    const float* a2  = (const float*)d_in[9];
    const float* bi2 = (const float*)d_in[10];

    float* out   = (float*)d_out;                 // (32, 1024)
    float* out_w = (float*)d_out + BB * 2 * DD;   // (32, 2048, 6)

    for (int blk = 0; blk < NBLK; blk++) {
        k_scores<<<dim3(NCH, BB), 256>>>(k, q, blk);
        k_attnv<<<dim3(LSPLIT, BB), 256>>>(v, out_w, blk);
        k_nf1<<<dim3(4, BB), 256>>>(W1, b1, a1, bi1, q, blk);
        k_f2<<<dim3(4, BB), 256>>>(W2, b2, blk);
        k_n2<<<BB, 512>>>(a2, bi2, out, blk);
    }
}

// round 5
// speedup vs baseline: 2.1307x; 1.0820x over previous
#include <cuda_runtime.h>
#include <cuda_fp16.h>
#include <math.h>

#define BB 32
#define LL 2048
#define DD 512
#define DFF 256
#define NBLK 6
#define EPSN 1e-6f
#define NCH 64            // score-stat chunks per batch (32 rows each)
#define LSPLIT 32         // attnv L-splits (64 rows each)
#define SCALE 0.04419417382415922f  // 1/sqrt(512)

// -------- device scratch (no allocations allowed) --------
__device__ __half2 g_kh2[(size_t)BB * LL * DD / 2];   // 64 MB fp16 k
__device__ __half2 g_vh2[(size_t)BB * LL * DD / 2];   // 64 MB fp16 v
__device__ float g_scores[BB * LL];
__device__ float g_m[BB][NCH];
__device__ float g_z[BB][NCH];
__device__ float g_Apart[LSPLIT][BB][DD];             // 2 MB deterministic partials
__device__ float g_q[BB * DD];                        // running q state
__device__ float g_qn[BB * DD];                       // post-norm1 q
__device__ float g_h[BB * DFF];                       // FFN hidden
__device__ float g_y[BB * DD];                        // pre-norm2

__device__ __forceinline__ unsigned int pack2(float a, float b) {
    __half2 h = __floats2half2_rn(a, b);
    return *reinterpret_cast<unsigned int*>(&h);
}

__device__ __forceinline__ float dot8h(uint4 u, float4 qa, float4 qb) {
    __half2 h0 = *(__half2*)&u.x, h1 = *(__half2*)&u.y;
    __half2 h2 = *(__half2*)&u.z, h3 = *(__half2*)&u.w;
    float2 f0 = __half22float2(h0), f1 = __half22float2(h1);
    float2 f2 = __half22float2(h2), f3 = __half22float2(h3);
    return f0.x * qa.x + f0.y * qa.y + f1.x * qa.z + f1.y * qa.w +
           f2.x * qb.x + f2.y * qb.y + f3.x * qb.z + f3.y * qb.w;
}

// -------- K1: scores + per-chunk stats; blk0 also converts k fp32->fp16 --------
// grid (NCH, BB), block 256: 8 warps x 4 rows
__global__ void k_scores(const float* __restrict__ kin, const float* __restrict__ qin, int blk) {
    const int b = blockIdx.y, tid = threadIdx.x;
    const int w = tid >> 5, lane = tid & 31;
    const int chunk = blockIdx.x;
    const int row0 = chunk * 32 + w * 4;

    const float* qsrc = (blk == 0) ? (qin + b * DD) : (g_q + b * DD);
    const float4* q4 = (const float4*)qsrc;
    const float4 qa = q4[2 * lane],        qb = q4[2 * lane + 1];
    const float4 qc = q4[2 * (lane + 32)], qd = q4[2 * (lane + 32) + 1];

    __shared__ float sc[32];
    float sr[4];

    if (blk == 0) {
#pragma unroll
        for (int r = 0; r < 4; r++) {
            const float4* kr = (const float4*)(kin + ((size_t)b * LL + row0 + r) * DD);
            float4 a0 = kr[2 * lane], a1 = kr[2 * lane + 1];
            float4 a2 = kr[2 * lane + 64], a3 = kr[2 * lane + 65];
            uint4* kw = (uint4*)((__half*)g_kh2 + ((size_t)b * LL + row0 + r) * DD);
            uint4 p0, p1;
            p0.x = pack2(a0.x, a0.y); p0.y = pack2(a0.z, a0.w);
            p0.z = pack2(a1.x, a1.y); p0.w = pack2(a1.z, a1.w);
            p1.x = pack2(a2.x, a2.y); p1.y = pack2(a2.z, a2.w);
            p1.z = pack2(a3.x, a3.y); p1.w = pack2(a3.z, a3.w);
            kw[lane] = p0; kw[lane + 32] = p1;
            float s = a0.x * qa.x + a0.y * qa.y + a0.z * qa.z + a0.w * qa.w
                    + a1.x * qb.x + a1.y * qb.y + a1.z * qb.z + a1.w * qb.w
                    + a2.x * qc.x + a2.y * qc.y + a2.z * qc.z + a2.w * qc.w
                    + a3.x * qd.x + a3.y * qd.y + a3.z * qd.z + a3.w * qd.w;
#pragma unroll
            for (int o = 16; o > 0; o >>= 1) s += __shfl_xor_sync(0xffffffffu, s, o);
            sr[r] = s * SCALE;
        }
    } else {
        uint4 u0[4], u1[4];
#pragma unroll
        for (int r = 0; r < 4; r++) {
            const uint4* kr = (const uint4*)((const __half*)g_kh2 +
                                             ((size_t)b * LL + row0 + r) * DD);
            u0[r] = kr[lane];
            u1[r] = kr[lane + 32];
        }
#pragma unroll
        for (int r = 0; r < 4; r++) {
            float s = dot8h(u0[r], qa, qb) + dot8h(u1[r], qc, qd);
#pragma unroll
            for (int o = 16; o > 0; o >>= 1) s += __shfl_xor_sync(0xffffffffu, s, o);
            sr[r] = s * SCALE;
        }
    }
    if (lane < 4) {
        const float v = sr[lane];
        g_scores[b * LL + row0 + lane] = v;
        sc[w * 4 + lane] = v;
    }
    __syncthreads();

    if (tid < 32) {
        const float s = sc[tid];
        float m = s;
#pragma unroll
        for (int o = 16; o > 0; o >>= 1) m = fmaxf(m, __shfl_xor_sync(0xffffffffu, m, o));
        float e = __expf(s - m);
#pragma unroll
        for (int o = 16; o > 0; o >>= 1) e += __shfl_xor_sync(0xffffffffu, e, o);
        if (tid == 0) { g_m[b][chunk] = m; g_z[b][chunk] = e; }
    }
}

// -------- K2: softmax finalize + weights out + A partials; blk0 converts v --------
// grid (LSPLIT, BB), block 256; thread owns 8 d's, 4-way row split
__global__ void k_attnv(const float* __restrict__ vin, float* __restrict__ out_w, int blk) {
    const int part = blockIdx.x, b = blockIdx.y;
    const int tid = threadIdx.x;
    __shared__ float se[64];
    __shared__ float s_m, s_inv;
    __shared__ float sacc[4][DD];

    if (tid < 32) {
        const float m0 = g_m[b][tid], m1 = g_m[b][tid + 32];
        const float z0 = g_z[b][tid], z1 = g_z[b][tid + 32];
        float m = fmaxf(m0, m1);
#pragma unroll
        for (int o = 16; o > 0; o >>= 1) m = fmaxf(m, __shfl_xor_sync(0xffffffffu, m, o));
        float z = z0 * __expf(m0 - m) + z1 * __expf(m1 - m);
#pragma unroll
        for (int o = 16; o > 0; o >>= 1) z += __shfl_xor_sync(0xffffffffu, z, o);
        if (tid == 0) { s_m = m; s_inv = 1.f / z; }
    }
    __syncthreads();
    if (tid < 64) {
        const int l = part * 64 + tid;
        const float e = __expf(g_scores[b * LL + l] - s_m) * s_inv;
        se[tid] = e;
        out_w[(size_t)(b * LL + l) * NBLK + blk] = e;
    }
    __syncthreads();

    const int dl = tid & 63;
    const int rg = tid >> 6;
    float acc[8] = {0.f, 0.f, 0.f, 0.f, 0.f, 0.f, 0.f, 0.f};

    if (blk == 0) {
#pragma unroll
        for (int l = rg; l < 64; l += 4) {
            const float4* vr = (const float4*)(vin + ((size_t)b * LL + part * 64 + l) * DD);
            float4 c0 = vr[2 * dl], c1 = vr[2 * dl + 1];
            uint4 p;
            p.x = pack2(c0.x, c0.y); p.y = pack2(c0.z, c0.w);
            p.z = pack2(c1.x, c1.y); p.w = pack2(c1.z, c1.w);
            ((uint4*)((__half*)g_vh2 + ((size_t)b * LL + part * 64 + l) * DD))[dl] = p;
            const float e = se[l];
            acc[0] += e * c0.x; acc[1] += e * c0.y; acc[2] += e * c0.z; acc[3] += e * c0.w;
            acc[4] += e * c1.x; acc[5] += e * c1.y; acc[6] += e * c1.z; acc[7] += e * c1.w;
        }
    } else {
        const __half* vb = (const __half*)g_vh2 + ((size_t)b * LL + part * 64) * DD;
#pragma unroll
        for (int l = rg; l < 64; l += 4) {
            uint4 u = ((const uint4*)(vb + (size_t)l * DD))[dl];
            const float e = se[l];
            __half2 h0 = *(__half2*)&u.x, h1 = *(__half2*)&u.y;
            __half2 h2 = *(__half2*)&u.z, h3 = *(__half2*)&u.w;
            float2 f0 = __half22float2(h0), f1 = __half22float2(h1);
            float2 f2 = __half22float2(h2), f3 = __half22float2(h3);
            acc[0] += e * f0.x; acc[1] += e * f0.y; acc[2] += e * f1.x; acc[3] += e * f1.y;
            acc[4] += e * f2.x; acc[5] += e * f2.y; acc[6] += e * f3.x; acc[7] += e * f3.y;
        }
    }
#pragma unroll
    for (int c = 0; c < 8; c++) sacc[rg][dl * 8 + c] = acc[c];
    __syncthreads();
#pragma unroll
    for (int rep = 0; rep < 2; rep++) {
        const int d = tid + rep * 256;
        g_Apart[part][b][d] = sacc[0][d] + sacc[1][d] + sacc[2][d] + sacc[3][d];
    }
}

// -------- shuffle block reduce over 256 threads (8 warps) --------
__device__ __forceinline__ float block_sum256(float val, float* red, int tid) {
#pragma unroll
    for (int o = 16; o > 0; o >>= 1) val += __shfl_xor_sync(0xffffffffu, val, o);
    if ((tid & 31) == 0) red[tid >> 5] = val;
    __syncthreads();
    if (tid < 32) {
        float v = (tid < 8) ? red[tid] : 0.f;
#pragma unroll
        for (int o = 4; o > 0; o >>= 1) v += __shfl_xor_sync(0xffffffffu, v, o);
        if (tid == 0) red[0] = v;
    }
    __syncthreads();
    const float r = red[0];
    __syncthreads();
    return r;
}

// -------- K3a: Apart reduce + norm1 + W1 GEMM slice (float4, high MLP) --------
// grid (4, BB), block 256; CTA (jc, b) owns 64 h-columns
__global__ void k_nf1(const float* __restrict__ W1, const float* __restrict__ b1,
                      const float* __restrict__ a1, const float* __restrict__ bi1,
                      const float* __restrict__ qin, int blk) {
    const int jc = blockIdx.x, b = blockIdx.y;
    const int tid = threadIdx.x;
    __shared__ float4 px[2][128];    // partial-sum halves
    __shared__ float qn_s[DD];
    __shared__ float hp[16][64];
    __shared__ float red[32];

    // Phase A: Apart reduce. thread (f4 = tid&127, half = tid>>7) sums 16 partials (float4)
    {
        const int f4 = tid & 127, half = tid >> 7;
        float4 x = make_float4(0.f, 0.f, 0.f, 0.f);
#pragma unroll
        for (int p = half * 16; p < half * 16 + 16; p++) {
            const float4 v = ((const float4*)g_Apart[p][b])[f4];
            x.x += v.x; x.y += v.y; x.z += v.z; x.w += v.w;
        }
        px[half][f4] = x;
    }
    __syncthreads();

    // Phase B: combine + residual + norm1 (threads 0..127 own float4 d-groups)
    float4 x = make_float4(0.f, 0.f, 0.f, 0.f);
    if (tid < 128) {
        const float4 r0 = px[0][tid], r1 = px[1][tid];
        const float4* res = (const float4*)((blk == 0) ? (qin + b * DD) : (g_q + b * DD));
        const float4 rr = res[tid];
        x.x = r0.x + r1.x + rr.x; x.y = r0.y + r1.y + rr.y;
        x.z = r0.z + r1.z + rr.z; x.w = r0.w + r1.w + rr.w;
    }
    const float mu = block_sum256((tid < 128) ? (x.x + x.y + x.z + x.w) : 0.f, red, tid) * (1.f / DD);
    float ssq = 0.f;
    float4 t = make_float4(0.f, 0.f, 0.f, 0.f);
    if (tid < 128) {
        t.x = x.x - mu; t.y = x.y - mu; t.z = x.z - mu; t.w = x.w - mu;
        ssq = t.x * t.x + t.y * t.y + t.z * t.z + t.w * t.w;
    }
    const float var = block_sum256(ssq, red, tid) * (1.f / (DD - 1));
    const float inv = 1.f / (sqrtf(var) + EPSN);
    if (tid < 128) {
        const float4 av = ((const float4*)(a1 + blk * DD))[tid];
        const float4 bv = ((const float4*)(bi1 + blk * DD))[tid];
        float4 qv;
        qv.x = av.x * t.x * inv + bv.x; qv.y = av.y * t.y * inv + bv.y;
        qv.z = av.z * t.z * inv + bv.z; qv.w = av.w * t.w * inv + bv.w;
        ((float4*)qn_s)[tid] = qv;
        if (jc == 0) ((float4*)(g_qn + b * DD))[tid] = qv;
    }
    __syncthreads();

    // Phase C: W1 slice. thread (j4 = tid&15, ds = tid>>4): 32 independent float4 loads
    {
        const int j4 = tid & 15, ds = tid >> 4;
        const float4* __restrict__ w1 =
            (const float4*)(W1 + (size_t)blk * DD * DFF) + jc * 16 + j4;
        float4 acc = make_float4(0.f, 0.f, 0.f, 0.f);
        const int d0 = ds * 32;
#pragma unroll
        for (int dd = 0; dd < 32; dd++) {
            const float4 wv = w1[(size_t)(d0 + dd) * (DFF / 4)];
            const float qd = qn_s[d0 + dd];
            acc.x += qd * wv.x; acc.y += qd * wv.y; acc.z += qd * wv.z; acc.w += qd * wv.w;
        }
        hp[ds][j4 * 4 + 0] = acc.x; hp[ds][j4 * 4 + 1] = acc.y;
        hp[ds][j4 * 4 + 2] = acc.z; hp[ds][j4 * 4 + 3] = acc.w;
    }
    __syncthreads();
    if (tid < 64) {
        const int jg = jc * 64 + tid;
        float s = b1[blk * DFF + jg];
#pragma unroll
        for (int ds = 0; ds < 16; ds++) s += hp[ds][tid];
        g_h[b * DFF + jg] = fmaxf(s, 0.f);
    }
}

// -------- K3b: W2 GEMM slice + residual -> y (float4, high MLP) --------
// grid (4, BB), block 256; CTA (dc, b) owns 128 d's
__global__ void k_f2(const float* __restrict__ W2, const float* __restrict__ b2, int blk) {
    const int dc = blockIdx.x, b = blockIdx.y;
    const int tid = threadIdx.x;
    __shared__ float h_s[DFF];
    __shared__ float fp[8][128];

    h_s[tid] = g_h[b * DFF + tid];
    __syncthreads();

    // thread (d4 = tid&31, js = tid>>5): 32 independent float4 loads
    {
        const int d4 = tid & 31, js = tid >> 5;
        const float4* __restrict__ w2 =
            (const float4*)(W2 + (size_t)blk * DFF * DD) + dc * 32 + d4;
        const int j0 = js * 32;
        float4 acc = make_float4(0.f, 0.f, 0.f, 0.f);
#pragma unroll
        for (int jj = 0; jj < 32; jj++) {
            const float4 wv = w2[(size_t)(j0 + jj) * (DD / 4)];
            const float hv = h_s[j0 + jj];
            acc.x += hv * wv.x; acc.y += hv * wv.y; acc.z += hv * wv.z; acc.w += hv * wv.w;
        }
        fp[js][d4 * 4 + 0] = acc.x; fp[js][d4 * 4 + 1] = acc.y;
        fp[js][d4 * 4 + 2] = acc.z; fp[js][d4 * 4 + 3] = acc.w;
    }
    __syncthreads();
    if (tid < 128) {
        const int dg = dc * 128 + tid;
        float s = g_qn[b * DD + dg] + b2[blk * DD + dg];
#pragma unroll
        for (int js = 0; js < 8; js++) s += fp[js][tid];
        g_y[b * DD + dg] = s;
    }
}

// -------- shuffle block reduce over 512 threads --------
__device__ __forceinline__ float block_sum512(float val, float* red, int tid) {
#pragma unroll
    for (int o = 16; o > 0; o >>= 1) val += __shfl_xor_sync(0xffffffffu, val, o);
    if ((tid & 31) == 0) red[tid >> 5] = val;
    __syncthreads();
    if (tid < 32) {
        float v = (tid < 16) ? red[tid] : 0.f;
#pragma unroll
        for (int o = 8; o > 0; o >>= 1) v += __shfl_xor_sync(0xffffffffu, v, o);
        if (tid == 0) red[0] = v;
    }
    __syncthreads();
    const float r = red[0];
    __syncthreads();
    return r;
}

// -------- K3c: norm2 + q update + out writes --------
// grid BB, block 512
__global__ void k_n2(const float* __restrict__ a2, const float* __restrict__ bi2,
                     float* __restrict__ out, int blk) {
    const int b = blockIdx.x;
    const int tid = threadIdx.x;
    __shared__ float red[32];

    const float y = g_y[b * DD + tid];
    const float mu = block_sum512(y, red, tid) * (1.f / DD);
    const float t = y - mu;
    const float var = block_sum512(t * t, red, tid) * (1.f / (DD - 1));
    const float inv = 1.f / (sqrtf(var) + EPSN);
    const float r = a2[blk * DD + tid] * t * inv + bi2[blk * DD + tid];
    g_q[b * DD + tid] = r;
    if (blk == 2) out[(size_t)b * 1024 + tid] = r;
    if (blk == 5) out[(size_t)b * 1024 + 512 + tid] = r;
}

extern "C" void kernel_launch(void* const* d_in, const int* in_sizes, int n_in,
                              void* d_out, int out_size) {
    const float* q   = (const float*)d_in[0];
    const float* k   = (const float*)d_in[1];
    const float* v   = (const float*)d_in[2];
    const float* W1  = (const float*)d_in[3];
    const float* b1  = (const float*)d_in[4];
    const float* W2  = (const float*)d_in[5];
    const float* b2  = (const float*)d_in[6];
    const float* a1  = (const float*)d_in[7];
    const float* bi1 = (const float*)d_in[8];
    const float* a2  = (const float*)d_in[9];
    const float* bi2 = (const float*)d_in[10];

    float* out   = (float*)d_out;                 // (32, 1024)
    float* out_w = (float*)d_out + BB * 2 * DD;   // (32, 2048, 6)

    for (int blk = 0; blk < NBLK; blk++) {
        k_scores<<<dim3(NCH, BB), 256>>>(k, q, blk);
        k_attnv<<<dim3(LSPLIT, BB), 256>>>(v, out_w, blk);
        k_nf1<<<dim3(4, BB), 256>>>(W1, b1, a1, bi1, q, blk);
        k_f2<<<dim3(4, BB), 256>>>(W2, b2, blk);
        k_n2<<<BB, 512>>>(a2, bi2, out, blk);
    }
}